// round 16
// baseline (speedup 1.0000x reference)
#include <cuda_runtime.h>

// PowerLinear, two kernels (stream-ordered, no in-kernel sync):
//   K1 (16 blocks): per-k-chunk c = colsum(R), cxp[b] = c_chunk . x_chunk,
//                   zero out.
//   K2 (256 blocks): W[b,j] = (n_b==0) ? cx_b : c_j d_j^{n_b} x[b,j];
//                    y += W_chunk @ R_chunk^T via RED atomics.
//   (n==0 rows of W are the constant cx_b, so no rank-1 epilogue is needed.)

#define DD 1024
#define KCHUNK 64
#define PADB 68
#define NPROD 16

__device__ float g_c[NPROD][64];     // final colsum per k-chunk
__device__ float g_cxp[NPROD][64];   // cx partials per k-chunk

__device__ __forceinline__ void redadd2(float* p, float a, float b)
{
    asm volatile("red.global.add.v2.f32 [%0], {%1, %2};"
                 :: "l"(p), "f"(a), "f"(b) : "memory");
}

// ---------------------------------------------------------------------------
// K1: 16 blocks, one per k-chunk. colsum + cx partial + zero out slice.
// ---------------------------------------------------------------------------
__global__ __launch_bounds__(256) void prep_kernel(const float* __restrict__ R,
                                                   const float* __restrict__ x,
                                                   float* __restrict__ out)
{
    __shared__ float pr[16][64];
    __shared__ float sm_c[64];

    const int p   = blockIdx.x;          // k-chunk
    const int tid = threadIdx.x;
    const int q   = tid & 15;            // 4-col quad
    const int g   = tid >> 4;            // 64-row group

    const float* base = R + p * KCHUNK + q * 4;
    float4 a = make_float4(0.f, 0.f, 0.f, 0.f);
#pragma unroll 16
    for (int r = 0; r < 64; r++) {
        float4 v = *(const float4*)(base + (g * 64 + r) * DD);
        a.x += v.x; a.y += v.y; a.z += v.z; a.w += v.w;
    }
    pr[g][q * 4 + 0] = a.x;
    pr[g][q * 4 + 1] = a.y;
    pr[g][q * 4 + 2] = a.z;
    pr[g][q * 4 + 3] = a.w;

    // zero this block's slice of out (4096 floats)
    {
        float4 z = make_float4(0.f, 0.f, 0.f, 0.f);
        float* po = out + p * 4096 + tid * 16;
        ((float4*)po)[0] = z; ((float4*)po)[1] = z;
        ((float4*)po)[2] = z; ((float4*)po)[3] = z;
    }

    __syncthreads();
    if (tid < 64) {
        float s = 0.f;
#pragma unroll
        for (int gg = 0; gg < 16; gg++) s += pr[gg][tid];
        sm_c[tid]  = s;
        g_c[p][tid] = s;
    }
    __syncthreads();

    // cx partial: thread b < 64 dots c-chunk with x[b, chunk]
    if (tid < 64) {
        const float* xb = x + tid * DD + p * KCHUNK;
        float cx = 0.f;
#pragma unroll
        for (int m = 0; m < 16; m++) {
            float4 xv = *(const float4*)(xb + m * 4);
            float4 cv = *(const float4*)&sm_c[m * 4];
            cx += cv.x * xv.x + cv.y * xv.y + cv.z * xv.z + cv.w * xv.w;
        }
        g_cxp[p][tid] = cx;
    }
}

// ---------------------------------------------------------------------------
// K2: 256 blocks = 16 i-tiles x 16 k-chunks, 256 threads, 2 blocks/SM.
// Scalar 4x4 register tiles, single-buffered 64x64 R tile, one main sync.
// ---------------------------------------------------------------------------
__global__ __launch_bounds__(256, 2)
void gemm_kernel(const float* __restrict__ x,
                 const int*   __restrict__ n,
                 const float* __restrict__ diag,
                 const float* __restrict__ R,
                 float*       __restrict__ out)
{
    __shared__ __align__(16) float sW[KCHUNK][PADB];   // W[k][b]
    __shared__ __align__(16) float sB[KCHUNK][PADB];   // R[k][i] transposed
    __shared__ float sm_c[64];
    __shared__ float sm_cx[64];

    const int bid = blockIdx.x;
    const int tid = threadIdx.x;
    const int it  = bid >> 4;
    const int ks  = bid & 15;
    const int i0  = it * 64;
    const int k0  = ks * KCHUNK;

    // ---- load R tile -------------------------------------------------------
    const int li = tid >> 2;            // row in tile (i)
    const int lk = (tid & 3) * 4;       // k offset {0,4,8,12}
    const float* rptr = R + (i0 + li) * DD + k0 + lk;
    float4 ra0 = *(const float4*)(rptr);
    float4 ra1 = *(const float4*)(rptr + 16);
    float4 ra2 = *(const float4*)(rptr + 32);
    float4 ra3 = *(const float4*)(rptr + 48);

    // ---- prologue: c chunk + global cx (cheap now) -------------------------
    if (tid < 64) {
        sm_c[tid] = g_c[ks][tid];
    } else if (tid < 128) {
        const int b = tid - 64;
        float s = 0.f;
#pragma unroll
        for (int p = 0; p < NPROD; p++) s += g_cxp[p][b];
        sm_cx[b] = s;
    }

    // ---- prefetch x/diag for W build ---------------------------------------
    const int wb = tid >> 2;            // b row this thread builds
    const int wq = (tid & 3) * 4;       // k quad base
    const int nb = n[wb];
    float4 xv[4], dv[4];
#pragma unroll
    for (int m = 0; m < 4; m++) {
        const int kk = wq + 16 * m;
        xv[m] = *(const float4*)(x + wb * DD + k0 + kk);
        dv[m] = *(const float4*)(diag + k0 + kk);
    }

    // store R tile transposed into sB
    {
        float4 rv[4] = {ra0, ra1, ra2, ra3};
#pragma unroll
        for (int s = 0; s < 4; s++) {
            const int kr = s * 16 + lk;
            sB[kr + 0][li] = rv[s].x;
            sB[kr + 1][li] = rv[s].y;
            sB[kr + 2][li] = rv[s].z;
            sB[kr + 3][li] = rv[s].w;
        }
    }
    __syncthreads();                     // sB, sm_c, sm_cx published

    // ---- build W tile (n0 rows = cx_b constant) ----------------------------
    {
        const float cxb = sm_cx[wb];
#pragma unroll
        for (int m = 0; m < 4; m++) {
            const int kk = wq + 16 * m;
            float xs[4] = {xv[m].x, xv[m].y, xv[m].z, xv[m].w};
            float ds[4] = {dv[m].x, dv[m].y, dv[m].z, dv[m].w};
#pragma unroll
            for (int c = 0; c < 4; c++) {
                float p = 1.f;
#pragma unroll
                for (int k = 0; k < 5; k++) p *= (k < nb) ? ds[c] : 1.f;
                sW[kk + c][wb] = (nb == 0) ? cxb : sm_c[kk + c] * xs[c] * p;
            }
        }
    }
    __syncthreads();

    // ---- main loop: 64 k iterations, 16 scalar FMAs each -------------------
    const int tx = tid & 15;
    const int ty = tid >> 4;
    const int i4 = tx * 4;
    const int b4 = ty * 4;

    float acc[4][4];
#pragma unroll
    for (int r = 0; r < 4; r++)
#pragma unroll
        for (int c = 0; c < 4; c++) acc[r][c] = 0.f;

#pragma unroll 16
    for (int kk = 0; kk < KCHUNK; kk++) {
        const float4 av = *(const float4*)&sW[kk][b4];
        const float4 bv = *(const float4*)&sB[kk][i4];
        acc[0][0] = fmaf(av.x, bv.x, acc[0][0]);
        acc[0][1] = fmaf(av.x, bv.y, acc[0][1]);
        acc[0][2] = fmaf(av.x, bv.z, acc[0][2]);
        acc[0][3] = fmaf(av.x, bv.w, acc[0][3]);
        acc[1][0] = fmaf(av.y, bv.x, acc[1][0]);
        acc[1][1] = fmaf(av.y, bv.y, acc[1][1]);
        acc[1][2] = fmaf(av.y, bv.z, acc[1][2]);
        acc[1][3] = fmaf(av.y, bv.w, acc[1][3]);
        acc[2][0] = fmaf(av.z, bv.x, acc[2][0]);
        acc[2][1] = fmaf(av.z, bv.y, acc[2][1]);
        acc[2][2] = fmaf(av.z, bv.z, acc[2][2]);
        acc[2][3] = fmaf(av.z, bv.w, acc[2][3]);
        acc[3][0] = fmaf(av.w, bv.x, acc[3][0]);
        acc[3][1] = fmaf(av.w, bv.y, acc[3][1]);
        acc[3][2] = fmaf(av.w, bv.z, acc[3][2]);
        acc[3][3] = fmaf(av.w, bv.w, acc[3][3]);
    }

    // ---- epilogue: pure vector atomics -------------------------------------
#pragma unroll
    for (int r = 0; r < 4; r++) {
        float* po = out + (b4 + r) * DD + i0 + i4;
        redadd2(po,     acc[r][0], acc[r][1]);
        redadd2(po + 2, acc[r][2], acc[r][3]);
    }
}

// ---------------------------------------------------------------------------
extern "C" void kernel_launch(void* const* d_in, const int* in_sizes, int n_in,
                              void* d_out, int out_size)
{
    const float* x    = (const float*)d_in[0];
    const int*   nn   = (const int*)  d_in[1];
    const float* diag = (const float*)d_in[2];
    const float* rot  = (const float*)d_in[3];
    float* out = (float*)d_out;

    prep_kernel<<<NPROD, 256>>>(rot, x, out);
    gemm_kernel<<<256, 256>>>(x, nn, diag, rot, out);
}

// round 17
// speedup vs baseline: 1.2199x; 1.2199x over previous
#include <cuda_runtime.h>

// PowerLinear, two kernels (stream-ordered):
//   K1 (64 blocks = 16 k-chunks x 4 row-groups):
//     partial colsums g_cp[p][g][64], partial cx g_cxp[p*4+g][b], zero out.
//   K2 (256 blocks): W[b,j] = (n_b==0) ? cx_b : c_j d_j^{n_b} x[b,j];
//     y += W_chunk @ R_chunk^T via RED atomics. (n0 rows constant => no
//     rank-1 epilogue needed.)

#define DD 1024
#define KCHUNK 64
#define PADB 68
#define NP1 64            // K1 grid

__device__ float g_cp[16][4][64];    // colsum partials [chunk][rowgroup][j]
__device__ float g_cxp[NP1][64];     // cx partials [block][b]

__device__ __forceinline__ void redadd2(float* p, float a, float b)
{
    asm volatile("red.global.add.v2.f32 [%0], {%1, %2};"
                 :: "l"(p), "f"(a), "f"(b) : "memory");
}

// ---------------------------------------------------------------------------
// K1: 64 blocks. Block (p,g): colsum partial over rows [256g,256g+256) of
// k-chunk p, cx partial, zero 1/64 of out.
// ---------------------------------------------------------------------------
__global__ __launch_bounds__(256) void prep_kernel(const float* __restrict__ R,
                                                   const float* __restrict__ x,
                                                   float* __restrict__ out)
{
    __shared__ float pr[16][64];
    __shared__ float sm_c[64];

    const int bid = blockIdx.x;
    const int p   = bid >> 2;            // k-chunk 0..15
    const int g   = bid & 3;             // row-group 0..3
    const int tid = threadIdx.x;
    const int q   = tid & 15;            // 4-col quad
    const int s   = tid >> 4;            // row subgroup 0..15

    const float* base = R + (g * 256 + s * 16) * DD + p * KCHUNK + q * 4;
    float4 a = make_float4(0.f, 0.f, 0.f, 0.f);
#pragma unroll
    for (int r = 0; r < 16; r++) {
        float4 v = *(const float4*)(base + r * DD);
        a.x += v.x; a.y += v.y; a.z += v.z; a.w += v.w;
    }
    pr[s][q * 4 + 0] = a.x;
    pr[s][q * 4 + 1] = a.y;
    pr[s][q * 4 + 2] = a.z;
    pr[s][q * 4 + 3] = a.w;

    // zero this block's slice of out (1024 floats)
    *(float4*)(out + bid * 1024 + tid * 4) =
        make_float4(0.f, 0.f, 0.f, 0.f);

    __syncthreads();
    if (tid < 64) {
        float c = 0.f;
#pragma unroll
        for (int ss = 0; ss < 16; ss++) c += pr[ss][tid];
        sm_c[tid] = c;
        g_cp[p][g][tid] = c;
    }
    __syncthreads();

    // cx partial: thread b < 64 dots this block's colsum partial with x chunk
    if (tid < 64) {
        const float* xb = x + tid * DD + p * KCHUNK;
        float cx = 0.f;
#pragma unroll
        for (int m = 0; m < 16; m++) {
            float4 xv = *(const float4*)(xb + m * 4);
            float4 cv = *(const float4*)&sm_c[m * 4];
            cx += cv.x * xv.x + cv.y * xv.y + cv.z * xv.z + cv.w * xv.w;
        }
        g_cxp[bid][tid] = cx;
    }
}

// ---------------------------------------------------------------------------
// K2: 256 blocks = 16 i-tiles x 16 k-chunks, 256 threads, 2 blocks/SM.
// Scalar 4x4 register tiles, single-buffered 64x64 R tile, one main sync.
// ---------------------------------------------------------------------------
__global__ __launch_bounds__(256, 2)
void gemm_kernel(const float* __restrict__ x,
                 const int*   __restrict__ n,
                 const float* __restrict__ diag,
                 const float* __restrict__ R,
                 float*       __restrict__ out)
{
    __shared__ __align__(16) float sW[KCHUNK][PADB];   // W[k][b]
    __shared__ __align__(16) float sB[KCHUNK][PADB];   // R[k][i] transposed
    __shared__ float sm_c[64];
    __shared__ float sm_cx[64];

    const int bid = blockIdx.x;
    const int tid = threadIdx.x;
    const int it  = bid >> 4;
    const int ks  = bid & 15;
    const int i0  = it * 64;
    const int k0  = ks * KCHUNK;

    // ---- load R tile -------------------------------------------------------
    const int li = tid >> 2;            // row in tile (i)
    const int lk = (tid & 3) * 4;       // k offset {0,4,8,12}
    const float* rptr = R + (i0 + li) * DD + k0 + lk;
    float4 ra0 = *(const float4*)(rptr);
    float4 ra1 = *(const float4*)(rptr + 16);
    float4 ra2 = *(const float4*)(rptr + 32);
    float4 ra3 = *(const float4*)(rptr + 48);

    // ---- prologue: c chunk (4 partials) + global cx (64 partials) ----------
    if (tid < 64) {
        sm_c[tid] = (g_cp[ks][0][tid] + g_cp[ks][1][tid]) +
                    (g_cp[ks][2][tid] + g_cp[ks][3][tid]);
    } else if (tid < 128) {
        const int b = tid - 64;
        float s0 = 0.f, s1 = 0.f, s2 = 0.f, s3 = 0.f;
#pragma unroll
        for (int q = 0; q < NP1; q += 4) {
            s0 += g_cxp[q + 0][b];
            s1 += g_cxp[q + 1][b];
            s2 += g_cxp[q + 2][b];
            s3 += g_cxp[q + 3][b];
        }
        sm_cx[b] = (s0 + s1) + (s2 + s3);
    }

    // ---- prefetch x/diag for W build ---------------------------------------
    const int wb = tid >> 2;            // b row this thread builds
    const int wq = (tid & 3) * 4;       // k quad base
    const int nb = n[wb];
    float4 xv[4], dv[4];
#pragma unroll
    for (int m = 0; m < 4; m++) {
        const int kk = wq + 16 * m;
        xv[m] = *(const float4*)(x + wb * DD + k0 + kk);
        dv[m] = *(const float4*)(diag + k0 + kk);
    }

    // store R tile transposed into sB
    {
        float4 rv[4] = {ra0, ra1, ra2, ra3};
#pragma unroll
        for (int s = 0; s < 4; s++) {
            const int kr = s * 16 + lk;
            sB[kr + 0][li] = rv[s].x;
            sB[kr + 1][li] = rv[s].y;
            sB[kr + 2][li] = rv[s].z;
            sB[kr + 3][li] = rv[s].w;
        }
    }
    __syncthreads();                     // sB, sm_c, sm_cx published

    // ---- build W tile (n0 rows = cx_b constant) ----------------------------
    {
        const float cxb = sm_cx[wb];
#pragma unroll
        for (int m = 0; m < 4; m++) {
            const int kk = wq + 16 * m;
            float xs[4] = {xv[m].x, xv[m].y, xv[m].z, xv[m].w};
            float ds[4] = {dv[m].x, dv[m].y, dv[m].z, dv[m].w};
#pragma unroll
            for (int c = 0; c < 4; c++) {
                float p = 1.f;
#pragma unroll
                for (int k = 0; k < 5; k++) p *= (k < nb) ? ds[c] : 1.f;
                sW[kk + c][wb] = (nb == 0) ? cxb : sm_c[kk + c] * xs[c] * p;
            }
        }
    }
    __syncthreads();

    // ---- main loop: 64 k iterations, 16 scalar FMAs each -------------------
    const int tx = tid & 15;
    const int ty = tid >> 4;
    const int i4 = tx * 4;
    const int b4 = ty * 4;

    float acc[4][4];
#pragma unroll
    for (int r = 0; r < 4; r++)
#pragma unroll
        for (int c = 0; c < 4; c++) acc[r][c] = 0.f;

#pragma unroll 16
    for (int kk = 0; kk < KCHUNK; kk++) {
        const float4 av = *(const float4*)&sW[kk][b4];
        const float4 bv = *(const float4*)&sB[kk][i4];
        acc[0][0] = fmaf(av.x, bv.x, acc[0][0]);
        acc[0][1] = fmaf(av.x, bv.y, acc[0][1]);
        acc[0][2] = fmaf(av.x, bv.z, acc[0][2]);
        acc[0][3] = fmaf(av.x, bv.w, acc[0][3]);
        acc[1][0] = fmaf(av.y, bv.x, acc[1][0]);
        acc[1][1] = fmaf(av.y, bv.y, acc[1][1]);
        acc[1][2] = fmaf(av.y, bv.z, acc[1][2]);
        acc[1][3] = fmaf(av.y, bv.w, acc[1][3]);
        acc[2][0] = fmaf(av.z, bv.x, acc[2][0]);
        acc[2][1] = fmaf(av.z, bv.y, acc[2][1]);
        acc[2][2] = fmaf(av.z, bv.z, acc[2][2]);
        acc[2][3] = fmaf(av.z, bv.w, acc[2][3]);
        acc[3][0] = fmaf(av.w, bv.x, acc[3][0]);
        acc[3][1] = fmaf(av.w, bv.y, acc[3][1]);
        acc[3][2] = fmaf(av.w, bv.z, acc[3][2]);
        acc[3][3] = fmaf(av.w, bv.w, acc[3][3]);
    }

    // ---- epilogue: pure vector atomics -------------------------------------
#pragma unroll
    for (int r = 0; r < 4; r++) {
        float* po = out + (b4 + r) * DD + i0 + i4;
        redadd2(po,     acc[r][0], acc[r][1]);
        redadd2(po + 2, acc[r][2], acc[r][3]);
    }
}

// ---------------------------------------------------------------------------
extern "C" void kernel_launch(void* const* d_in, const int* in_sizes, int n_in,
                              void* d_out, int out_size)
{
    const float* x    = (const float*)d_in[0];
    const int*   nn   = (const int*)  d_in[1];
    const float* diag = (const float*)d_in[2];
    const float* rot  = (const float*)d_in[3];
    float* out = (float*)d_out;

    prep_kernel<<<NP1, 256>>>(rot, x, out);
    gemm_kernel<<<256, 256>>>(x, nn, diag, rot, out);
}